// round 4
// baseline (speedup 1.0000x reference)
#include <cuda_runtime.h>

// Problem constants
#define Bv 8
#define Nv 128
#define Dv 256
#define Hv 128
#define Kv 8

// Scratch (allocation-free rule: __device__ globals)
__device__ float g_Ai [Bv * Nv * Hv];   // [b*N+i][h]        : E @ W1a^T
__device__ float g_AjT[Bv * Hv * Nv];   // [b][h][j]         : (E @ W1b^T) + b1, transposed per batch
__device__ float g_Wq [Hv * Kv];        // [h][k]
__device__ float g_bq [Kv];

// ---------------------------------------------------------------------------
// Kernel 1: one GEMM for both halves.
//   Treat output cols 0..127   -> Ai (h = col),        W1[h][d]
//         output cols 128..255 -> Aj (h = col-128),    W1[h][256+d]
// Block tile: 32 rows x 64 cols, K=256 in chunks of 32. 256 threads,
// thread tile 2x4. Grid = (4 col-tiles, 32 row-tiles) = 128 blocks (1 wave).
// ---------------------------------------------------------------------------
__global__ void __launch_bounds__(256) k1_gemm(const float* __restrict__ E,
                                               const float* __restrict__ W1,
                                               const float* __restrict__ b1)
{
    __shared__ float Es[32 * 36];   // [k][m], row padded to 36
    __shared__ float Ws[32 * 68];   // [k][c], row padded to 68

    const int ct   = blockIdx.x;          // 0..3 (col tile of 64)
    const int mt   = blockIdx.y;          // 0..31 (row tile of 32)
    const int tid  = threadIdx.x;
    const int tx   = tid & 15;            // 16 col-groups of 4
    const int ty   = tid >> 4;            // 16 row-groups of 2
    const int row0 = mt * 32;
    const bool isB = (ct >= 2);
    const int hbase = (isB ? (ct - 2) : ct) * 64;   // h of col 0 of this tile
    const int dofs  = isB ? Dv : 0;                 // offset into W1 row

    float acc[2][4];
#pragma unroll
    for (int r = 0; r < 2; r++)
#pragma unroll
        for (int c = 0; c < 4; c++) acc[r][c] = 0.0f;

    for (int kc = 0; kc < Dv; kc += 32) {
        // Load E tile (32 rows x 32 k), store transposed [k][m]. Coalesced LDG.
        for (int idx = tid; idx < 32 * 32; idx += 256) {
            int m = idx >> 5, k = idx & 31;
            Es[k * 36 + m] = E[(row0 + m) * Dv + kc + k];
        }
        // Load W tile (64 cols x 32 k), store [k][c]. Coalesced LDG over k.
        for (int idx = tid; idx < 64 * 32; idx += 256) {
            int c = idx >> 5, k = idx & 31;
            Ws[k * 68 + c] = W1[(hbase + c) * (2 * Dv) + dofs + kc + k];
        }
        __syncthreads();

#pragma unroll
        for (int k = 0; k < 32; k++) {
            float2 av = *(const float2*)&Es[k * 36 + 2 * ty];
            float4 bv = *(const float4*)&Ws[k * 68 + 4 * tx];
            acc[0][0] = fmaf(av.x, bv.x, acc[0][0]);
            acc[0][1] = fmaf(av.x, bv.y, acc[0][1]);
            acc[0][2] = fmaf(av.x, bv.z, acc[0][2]);
            acc[0][3] = fmaf(av.x, bv.w, acc[0][3]);
            acc[1][0] = fmaf(av.y, bv.x, acc[1][0]);
            acc[1][1] = fmaf(av.y, bv.y, acc[1][1]);
            acc[1][2] = fmaf(av.y, bv.z, acc[1][2]);
            acc[1][3] = fmaf(av.y, bv.w, acc[1][3]);
        }
        __syncthreads();
    }

#pragma unroll
    for (int r = 0; r < 2; r++) {
        int grow = row0 + 2 * ty + r;          // global row = b*N + i
#pragma unroll
        for (int c = 0; c < 4; c++) {
            int h = hbase + 4 * tx + c;
            if (!isB) {
                g_Ai[grow * Hv + h] = acc[r][c];
            } else {
                int b = grow >> 7;             // N = 128
                int i = grow & 127;
                g_AjT[(b * Hv + h) * Nv + i] = acc[r][c] + b1[h];
            }
        }
    }
}

// ---------------------------------------------------------------------------
// Kernel 2: Wq[h][k] = sum_d W2[d][h] * q[k][d];  bq[k] = sum_d b2[d]*q[k][d]
// Grid = K blocks of 128 threads (thread == h). W2 reads coalesced over h.
// ---------------------------------------------------------------------------
__global__ void __launch_bounds__(128) k2_wq(const float* __restrict__ W2,
                                             const float* __restrict__ b2,
                                             const float* __restrict__ q)
{
    __shared__ float qs[Dv];
    const int k   = blockIdx.x;
    const int tid = threadIdx.x;

    for (int d = tid; d < Dv; d += 128) qs[d] = q[k * Dv + d];
    __syncthreads();

    float s = 0.0f;
#pragma unroll 8
    for (int d = 0; d < Dv; d++) s = fmaf(W2[d * Hv + tid], qs[d], s);
    g_Wq[tid * Kv + k] = s;

    if (tid == 0) {
        float t = 0.0f;
        for (int d = 0; d < Dv; d++) t = fmaf(b2[d], qs[d], t);
        g_bq[k] = t;
    }
}

// ---------------------------------------------------------------------------
// Kernel 3 (dominant): fused relu-GEMV + sigmoid + diagonal mask.
// Block = (b, i-tile of 16, j-tile of 64), 256 threads; thread owns 1 i, 4 j.
// Grid = (2, 8, 8) = 128 blocks -> single wave on 148 SMs.
// Inner loop per h: 1 LDS + 3 LDS.128, 4 FADD, 4 FMNMX, 32 FFMA -> FMA-bound.
// ---------------------------------------------------------------------------
__global__ void __launch_bounds__(256) k3_main(float* __restrict__ out)
{
    __shared__ float sAi[16][Hv];     // 8 KB
    __shared__ float sAj[Hv][64];     // 32 KB  ([h][j], b1 pre-added)
    __shared__ float sWq[Hv * Kv];    // 4 KB
    __shared__ float sBq[Kv];

    const int jt = blockIdx.x, it = blockIdx.y, b = blockIdx.z;
    const int j0 = jt * 64, i0 = it * 16;
    const int tid = threadIdx.x;

    for (int idx = tid; idx < Hv * 64; idx += 256) {
        int h = idx >> 6, j = idx & 63;
        sAj[h][j] = g_AjT[(b * Hv + h) * Nv + j0 + j];
    }
    for (int idx = tid; idx < 16 * Hv; idx += 256) {
        int i = idx >> 7, h = idx & 127;
        sAi[i][h] = g_Ai[(b * Nv + i0 + i) * Hv + h];
    }
    for (int idx = tid; idx < Hv * Kv; idx += 256) sWq[idx] = g_Wq[idx];
    if (tid < Kv) sBq[tid] = g_bq[tid];
    __syncthreads();

    const int i  = tid >> 4;          // 0..15
    const int jb = (tid & 15) * 4;    // 0,4,...,60

    float acc[4][Kv];
#pragma unroll
    for (int jj = 0; jj < 4; jj++)
#pragma unroll
        for (int k = 0; k < Kv; k++) acc[jj][k] = 0.0f;

#pragma unroll 8
    for (int h = 0; h < Hv; h++) {
        float  ai = sAi[i][h];
        float4 aj = *(const float4*)&sAj[h][jb];
        float4 w0 = *(const float4*)&sWq[h * Kv];
        float4 w1 = *(const float4*)&sWq[h * Kv + 4];
        float s[4];
        s[0] = fmaxf(ai + aj.x, 0.0f);
        s[1] = fmaxf(ai + aj.y, 0.0f);
        s[2] = fmaxf(ai + aj.z, 0.0f);
        s[3] = fmaxf(ai + aj.w, 0.0f);
        float w[8] = {w0.x, w0.y, w0.z, w0.w, w1.x, w1.y, w1.z, w1.w};
#pragma unroll
        for (int jj = 0; jj < 4; jj++)
#pragma unroll
            for (int k = 0; k < Kv; k++)
                acc[jj][k] = fmaf(s[jj], w[k], acc[jj][k]);
    }

    const int gi = i0 + i;
    const int dj = gi - (j0 + jb);    // diagonal lane within our 4 j's, if any
#pragma unroll
    for (int k = 0; k < Kv; k++) {
        float bk = sBq[k];
        float4 v;
        v.x = __fdividef(1.0f, 1.0f + __expf(-(acc[0][k] + bk)));
        v.y = __fdividef(1.0f, 1.0f + __expf(-(acc[1][k] + bk)));
        v.z = __fdividef(1.0f, 1.0f + __expf(-(acc[2][k] + bk)));
        v.w = __fdividef(1.0f, 1.0f + __expf(-(acc[3][k] + bk)));
        if      (dj == 0) v.x = 0.0f;
        else if (dj == 1) v.y = 0.0f;
        else if (dj == 2) v.z = 0.0f;
        else if (dj == 3) v.w = 0.0f;
        *(float4*)&out[(((b * Kv + k) * Nv + gi) << 7) + j0 + jb] = v;
    }
}

// ---------------------------------------------------------------------------
extern "C" void kernel_launch(void* const* d_in, const int* in_sizes, int n_in,
                              void* d_out, int out_size)
{
    const float* E  = (const float*)d_in[0];
    const float* W1 = (const float*)d_in[1];
    const float* b1 = (const float*)d_in[2];
    const float* W2 = (const float*)d_in[3];
    const float* b2 = (const float*)d_in[4];
    const float* q  = (const float*)d_in[5];
    float* out = (float*)d_out;

    k1_gemm<<<dim3(4, 32), 256>>>(E, W1, b1);
    k2_wq  <<<Kv, 128>>>(W2, b2, q);
    k3_main<<<dim3(2, 8, 8), 256>>>(out);
}

// round 9
// speedup vs baseline: 1.5719x; 1.5719x over previous
#include <cuda_runtime.h>

// Problem constants
#define Bv 8
#define Nv 128
#define Dv 256
#define Hv 128
#define Kv 8

// Scratch (allocation-free rule: __device__ globals)
__device__ float g_Ai [Bv * Nv * Hv];   // [b*N+i][h]        : E @ W1a^T
__device__ float g_AjT[Bv * Hv * Nv];   // [b][h][j]         : (E @ W1b^T) + b1
__device__ float g_Wq [Hv * Kv];        // [h][k]
__device__ float g_bq [Kv];

// ---- packed fp32x2 helpers (sm_103a FFMA2 path, only reachable via PTX) ----
__device__ __forceinline__ unsigned long long pack2(float x, float y) {
    unsigned long long r;
    asm("mov.b64 %0, {%1, %2};" : "=l"(r) : "f"(x), "f"(y));
    return r;
}
__device__ __forceinline__ void unpack2(unsigned long long v, float& x, float& y) {
    asm("mov.b64 {%0, %1}, %2;" : "=f"(x), "=f"(y) : "l"(v));
}
__device__ __forceinline__ unsigned long long fma2(unsigned long long a,
                                                   unsigned long long b,
                                                   unsigned long long c) {
    unsigned long long d;
    asm("fma.rn.f32x2 %0, %1, %2, %3;" : "=l"(d) : "l"(a), "l"(b), "l"(c));
    return d;
}

// ---------------------------------------------------------------------------
// Kernel 1 (fused with k2): GEMM for both W1 halves + tiny Wq/bq blocks.
// GEMM blocks 0..255: tile 16 rows x 64 cols, K=256 in chunks of 32,
//   128 threads, thread tile 2x4, register double-buffered global loads
//   (LDG of chunk c+1 overlaps compute of chunk c). Packed FFMA2 inner loop.
// Blocks 256..263: Wq[h][k], bq[k] (k = blk-256), overlap the GEMM wave.
// ---------------------------------------------------------------------------
__global__ void __launch_bounds__(128) k1_fused(const float* __restrict__ E,
                                                const float* __restrict__ W1,
                                                const float* __restrict__ b1,
                                                const float* __restrict__ W2,
                                                const float* __restrict__ b2,
                                                const float* __restrict__ q)
{
    __shared__ float Es[2][32 * 18];   // [buf][k][m], m-pad 18
    __shared__ float Ws[2][32 * 68];   // [buf][k][c], c-pad 68
    __shared__ float qs[Dv];

    const int blk = blockIdx.x;
    const int tid = threadIdx.x;

    if (blk >= 256) {
        // ---- k2: Wq[h][k] = sum_d W2[d][h]*q[k][d], bq[k] = b2·q[k] ----
        const int k = blk - 256;
        for (int d = tid; d < Dv; d += 128) qs[d] = q[k * Dv + d];
        __syncthreads();
        float s = 0.0f;
#pragma unroll 16
        for (int d = 0; d < Dv; d++) s = fmaf(W2[d * Hv + tid], qs[d], s);
        g_Wq[tid * Kv + k] = s;
        if (tid == 0) {
            float t = 0.0f;
            for (int d = 0; d < Dv; d++) t = fmaf(b2[d], qs[d], t);
            g_bq[k] = t;
        }
        return;
    }

    // ---- GEMM block ----
    const int ct = blk & 3;               // col tile (64 cols)
    const int mt = blk >> 2;              // row tile (16 rows), 0..63
    const int tx = tid & 15;              // cols 4*tx
    const int ty = tid >> 4;              // rows 2*ty (0..7)
    const int row0  = mt * 16;
    const bool isB  = (ct >= 2);
    const int hbase = (isB ? (ct - 2) : ct) * 64;
    const int dofs  = isB ? Dv : 0;

    // element ownership for staging (fixed per thread across chunks)
    const int ek = tid & 31;              // k within chunk (E and W)
    const int em = tid >> 5;              // +4u  -> m (E), c (W) base

    float eR[4], wR[16];
    // prefetch chunk 0
    {
        const float* Ep = E + (long)(row0 + em) * Dv + ek;
#pragma unroll
        for (int u = 0; u < 4; u++) eR[u] = Ep[u * 4 * Dv];
        const float* Wp = W1 + (long)(hbase + em) * (2 * Dv) + dofs + ek;
#pragma unroll
        for (int u = 0; u < 16; u++) wR[u] = Wp[u * 4 * (2 * Dv)];
    }

    unsigned long long acc[2][2];
    acc[0][0] = acc[0][1] = acc[1][0] = acc[1][1] = 0ULL;

    for (int c = 0; c < 8; c++) {
        const int buf = c & 1;
        // stage current chunk into smem (transposed)
#pragma unroll
        for (int u = 0; u < 4; u++)  Es[buf][ek * 18 + em + 4 * u] = eR[u];
#pragma unroll
        for (int u = 0; u < 16; u++) Ws[buf][ek * 68 + em + 4 * u] = wR[u];
        __syncthreads();

        // issue LDG for next chunk; latency overlaps the compute below
        if (c < 7) {
            const int kc = (c + 1) * 32;
            const float* Ep = E + (long)(row0 + em) * Dv + kc + ek;
#pragma unroll
            for (int u = 0; u < 4; u++) eR[u] = Ep[u * 4 * Dv];
            const float* Wp = W1 + (long)(hbase + em) * (2 * Dv) + dofs + kc + ek;
#pragma unroll
            for (int u = 0; u < 16; u++) wR[u] = Wp[u * 4 * (2 * Dv)];
        }

#pragma unroll
        for (int k = 0; k < 32; k++) {
            float2 av = *(const float2*)&Es[buf][k * 18 + 2 * ty];
            ulonglong2 bv = *(const ulonglong2*)&Ws[buf][k * 68 + 4 * tx];
            unsigned long long ax = pack2(av.x, av.x);
            unsigned long long ay = pack2(av.y, av.y);
            acc[0][0] = fma2(ax, bv.x, acc[0][0]);
            acc[0][1] = fma2(ax, bv.y, acc[0][1]);
            acc[1][0] = fma2(ay, bv.x, acc[1][0]);
            acc[1][1] = fma2(ay, bv.y, acc[1][1]);
        }
        __syncthreads();
    }

    // epilogue
#pragma unroll
    for (int r = 0; r < 2; r++) {
        const int grow = row0 + 2 * ty + r;        // b*N + i
        float v[4];
        unpack2(acc[r][0], v[0], v[1]);
        unpack2(acc[r][1], v[2], v[3]);
#pragma unroll
        for (int cc = 0; cc < 4; cc++) {
            const int h = hbase + 4 * tx + cc;
            if (!isB) {
                g_Ai[grow * Hv + h] = v[cc];
            } else {
                const int b = grow >> 7, i = grow & 127;
                g_AjT[(b * Hv + h) * Nv + i] = v[cc] + b1[h];
            }
        }
    }
}

// ---------------------------------------------------------------------------
// Kernel 3 (dominant): fused relu-GEMV + sigmoid + diagonal mask.
// Block = (b, i-tile 16, j-tile 64), 256 threads; thread owns 1 i, 4 j.
// Inner loop per h: 16 packed FFMA2 (32 MACs) instead of 32 FFMA.
// ---------------------------------------------------------------------------
__global__ void __launch_bounds__(256) k3_main(float* __restrict__ out)
{
    __shared__ float sAi[16][Hv];     // 8 KB
    __shared__ float sAj[Hv][64];     // 32 KB  ([h][j], b1 pre-added)
    __shared__ float sWq[Hv * Kv];    // 4 KB
    __shared__ float sBq[Kv];

    const int jt = blockIdx.x, it = blockIdx.y, b = blockIdx.z;
    const int j0 = jt * 64, i0 = it * 16;
    const int tid = threadIdx.x;

    for (int idx = tid; idx < Hv * 64; idx += 256) {
        int h = idx >> 6, j = idx & 63;
        sAj[h][j] = g_AjT[(b * Hv + h) * Nv + j0 + j];
    }
    for (int idx = tid; idx < 16 * Hv; idx += 256) {
        int i = idx >> 7, h = idx & 127;
        sAi[i][h] = g_Ai[(b * Nv + i0 + i) * Hv + h];
    }
    for (int idx = tid; idx < Hv * Kv; idx += 256) sWq[idx] = g_Wq[idx];
    if (tid < Kv) sBq[tid] = g_bq[tid];
    __syncthreads();

    const int i  = tid >> 4;          // 0..15
    const int jb = (tid & 15) * 4;    // 0,4,...,60

    unsigned long long acc[4][4];     // [jj][k-pair]
#pragma unroll
    for (int jj = 0; jj < 4; jj++)
#pragma unroll
        for (int p = 0; p < 4; p++) acc[jj][p] = 0ULL;

#pragma unroll 4
    for (int h = 0; h < Hv; h++) {
        float  ai = sAi[i][h];
        float4 aj = *(const float4*)&sAj[h][jb];
        ulonglong2 w0 = *(const ulonglong2*)&sWq[h * Kv];     // pairs (k0,k1),(k2,k3)
        ulonglong2 w1 = *(const ulonglong2*)&sWq[h * Kv + 4]; // pairs (k4,k5),(k6,k7)
        float s0 = fmaxf(ai + aj.x, 0.0f);
        float s1 = fmaxf(ai + aj.y, 0.0f);
        float s2 = fmaxf(ai + aj.z, 0.0f);
        float s3 = fmaxf(ai + aj.w, 0.0f);
        unsigned long long sp[4] = { pack2(s0, s0), pack2(s1, s1),
                                     pack2(s2, s2), pack2(s3, s3) };
#pragma unroll
        for (int jj = 0; jj < 4; jj++) {
            acc[jj][0] = fma2(sp[jj], w0.x, acc[jj][0]);
            acc[jj][1] = fma2(sp[jj], w0.y, acc[jj][1]);
            acc[jj][2] = fma2(sp[jj], w1.x, acc[jj][2]);
            acc[jj][3] = fma2(sp[jj], w1.y, acc[jj][3]);
        }
    }

    const int gi = i0 + i;
    const int dj = gi - (j0 + jb);    // diagonal lane within our 4 j's, if any

    float a[4][Kv];
#pragma unroll
    for (int jj = 0; jj < 4; jj++)
#pragma unroll
        for (int p = 0; p < 4; p++)
            unpack2(acc[jj][p], a[jj][2 * p], a[jj][2 * p + 1]);

#pragma unroll
    for (int k = 0; k < Kv; k++) {
        float bk = sBq[k];
        float4 v;
        v.x = __fdividef(1.0f, 1.0f + __expf(-(a[0][k] + bk)));
        v.y = __fdividef(1.0f, 1.0f + __expf(-(a[1][k] + bk)));
        v.z = __fdividef(1.0f, 1.0f + __expf(-(a[2][k] + bk)));
        v.w = __fdividef(1.0f, 1.0f + __expf(-(a[3][k] + bk)));
        if      (dj == 0) v.x = 0.0f;
        else if (dj == 1) v.y = 0.0f;
        else if (dj == 2) v.z = 0.0f;
        else if (dj == 3) v.w = 0.0f;
        *(float4*)&out[(((b * Kv + k) * Nv + gi) << 7) + j0 + jb] = v;
    }
}

// ---------------------------------------------------------------------------
extern "C" void kernel_launch(void* const* d_in, const int* in_sizes, int n_in,
                              void* d_out, int out_size)
{
    const float* E  = (const float*)d_in[0];
    const float* W1 = (const float*)d_in[1];
    const float* b1 = (const float*)d_in[2];
    const float* W2 = (const float*)d_in[3];
    const float* b2 = (const float*)d_in[4];
    const float* q  = (const float*)d_in[5];
    float* out = (float*)d_out;

    k1_fused<<<264, 128>>>(E, W1, b1, W2, b2, q);
    k3_main<<<dim3(2, 8, 8), 256>>>(out);
}